// round 4
// baseline (speedup 1.0000x reference)
#include <cuda_runtime.h>
#include <math.h>
#include <stdint.h>

#define N_NODES  50000
#define N_EDGES  800000
#define N_GRAPHS 256
#define DMAX     512
#define GRUH     256

// ---------------- scratch (device globals; no allocation allowed) ----------------
__device__ __align__(16) float g_h   [(size_t)N_NODES * DMAX];
__device__ __align__(16) float g_buf0[(size_t)N_NODES * DMAX];
__device__ __align__(16) float g_buf1[(size_t)N_NODES * DMAX];
__device__ float g_dinv[N_NODES];
__device__ int   g_counts[N_NODES];
__device__ int   g_cursor[N_NODES];
__device__ int   g_offs[N_NODES + 1];
__device__ int   g_csrc[N_EDGES];
__device__ int   g_gcounts[N_GRAPHS];
__device__ int   g_goffs[N_GRAPHS + 1];
__device__ float g_gate[N_NODES];
__device__ __align__(16) float g_emb[N_GRAPHS * 512];
__device__ float g_h1[N_GRAPHS * GRUH];
__device__ float g_h2[N_GRAPHS * GRUH];
__device__ int   g_is64;

// ---------------- index-width detection (int64 vs int32 inputs) ----------------
// If edge_index is int64, every odd 32-bit word (high half of values < 50000) is 0.
// If int32, odd words are random node ids — all-zero over 128 samples is impossible.
__global__ void detect_kernel(const int* __restrict__ ei_raw) {
    if (blockIdx.x == 0 && threadIdx.x == 0) {
        int is64 = 1;
        for (int i = 0; i < 128; i++) {
            if (ei_raw[2 * i + 1] != 0) { is64 = 0; break; }
        }
        g_is64 = is64;
    }
}

__device__ __forceinline__ int load_idx(const void* p, long long i, int is64) {
    return is64 ? (int)((const long long*)p)[i] : ((const int*)p)[i];
}

// ---------------- init / degree count / CSR build ----------------
__global__ void init_kernel() {
    int i = blockIdx.x * blockDim.x + threadIdx.x;
    int stride = gridDim.x * blockDim.x;
    for (int k = i; k < N_NODES; k += stride) { g_counts[k] = 0; g_cursor[k] = 0; }
    for (int k = i; k < N_GRAPHS; k += stride) g_gcounts[k] = 0;
}

__global__ void count_kernel(const void* __restrict__ ei, const void* __restrict__ batch) {
    int is64 = g_is64;
    int i = blockIdx.x * blockDim.x + threadIdx.x;
    int stride = gridDim.x * blockDim.x;
    for (int e = i; e < N_EDGES; e += stride) {
        int d = load_idx(ei, (long long)N_EDGES + e, is64);   // dst = edge_index[1]
        atomicAdd(&g_counts[d], 1);
    }
    for (int v = i; v < N_NODES; v += stride) {
        int b = load_idx(batch, v, is64);
        atomicAdd(&g_gcounts[b], 1);
    }
}

__device__ void scan_array(const int* __restrict__ in, int n, int* __restrict__ out, int* sh) {
    int tid = threadIdx.x;
    int base = 0;
    for (int start = 0; start < n; start += 1024) {
        int i = start + tid;
        int v = (i < n) ? in[i] : 0;
        sh[tid] = v;
        __syncthreads();
        for (int d = 1; d < 1024; d <<= 1) {
            int t = (tid >= d) ? sh[tid - d] : 0;
            __syncthreads();
            sh[tid] += t;
            __syncthreads();
        }
        if (i < n) out[i] = base + sh[tid] - v;  // exclusive prefix
        base += sh[1023];
        __syncthreads();
    }
    if (tid == 0) out[n] = base;
}

__global__ void __launch_bounds__(1024) scan_kernel() {
    __shared__ int sh[1024];
    scan_array(g_counts, N_NODES, g_offs, sh);
    __syncthreads();
    scan_array(g_gcounts, N_GRAPHS, g_goffs, sh);
}

__global__ void dinv_kernel() {
    int i = blockIdx.x * blockDim.x + threadIdx.x;
    if (i < N_NODES) g_dinv[i] = rsqrtf((float)(g_counts[i] + 1));  // +1 self-loop; deg>=1
}

__global__ void fill_kernel(const void* __restrict__ ei) {
    int is64 = g_is64;
    int i = blockIdx.x * blockDim.x + threadIdx.x;
    int stride = gridDim.x * blockDim.x;
    for (int e = i; e < N_EDGES; e += stride) {
        int d = load_idx(ei, (long long)N_EDGES + e, is64);
        int s = load_idx(ei, e, is64);
        int pos = g_offs[d] + atomicAdd(&g_cursor[d], 1);
        g_csrc[pos] = s;
    }
}

// ---------------- SGEMM: C[M,N] = A[M,K] @ B[K,N] (fp32, 128x128x16 tiles) ----------------
#define BM 128
#define BN 128
#define BKK 16

__global__ void __launch_bounds__(256) sgemm_kernel(
    const float* __restrict__ A, const float* __restrict__ B, float* __restrict__ C,
    int M, int N, int K)
{
    __shared__ __align__(16) float As[BKK][BM];
    __shared__ __align__(16) float Bs[BKK][BN];
    int tid = threadIdx.x;
    int row0 = blockIdx.x * BM;
    int col0 = blockIdx.y * BN;
    int tx = tid & 15, ty = tid >> 4;

    float acc[8][8];
#pragma unroll
    for (int i = 0; i < 8; i++)
#pragma unroll
        for (int j = 0; j < 8; j++) acc[i][j] = 0.f;

    for (int k0 = 0; k0 < K; k0 += BKK) {
        // load A tile (transposed into smem), guarded on M
#pragma unroll
        for (int l = 0; l < 2; l++) {
            int f = tid + l * 256;
            int r = f >> 2;
            int c4 = f & 3;
            int grow = row0 + r;
            float4 v = make_float4(0.f, 0.f, 0.f, 0.f);
            if (grow < M) v = *(const float4*)(A + (size_t)grow * K + k0 + c4 * 4);
            As[c4 * 4 + 0][r] = v.x;
            As[c4 * 4 + 1][r] = v.y;
            As[c4 * 4 + 2][r] = v.z;
            As[c4 * 4 + 3][r] = v.w;
        }
        // load B tile (K, N both multiples of tile dims)
#pragma unroll
        for (int l = 0; l < 2; l++) {
            int f = tid + l * 256;
            int kk = f >> 5;
            int c4 = f & 31;
            float4 v = *(const float4*)(B + (size_t)(k0 + kk) * N + col0 + c4 * 4);
            *(float4*)&Bs[kk][c4 * 4] = v;
        }
        __syncthreads();
#pragma unroll
        for (int kk = 0; kk < BKK; kk++) {
            float a[8], b[8];
            *(float4*)&a[0] = *(const float4*)&As[kk][ty * 8];
            *(float4*)&a[4] = *(const float4*)&As[kk][ty * 8 + 4];
            *(float4*)&b[0] = *(const float4*)&Bs[kk][tx * 8];
            *(float4*)&b[4] = *(const float4*)&Bs[kk][tx * 8 + 4];
#pragma unroll
            for (int i = 0; i < 8; i++)
#pragma unroll
                for (int j = 0; j < 8; j++)
                    acc[i][j] += a[i] * b[j];
        }
        __syncthreads();
    }
#pragma unroll
    for (int i = 0; i < 8; i++) {
        int grow = row0 + ty * 8 + i;
        if (grow < M) {
            float* crow = C + (size_t)grow * N + col0 + tx * 8;
            *(float4*)(crow)     = make_float4(acc[i][0], acc[i][1], acc[i][2], acc[i][3]);
            *(float4*)(crow + 4) = make_float4(acc[i][4], acc[i][5], acc[i][6], acc[i][7]);
        }
    }
}

// ---------------- GCN aggregation (CSR by dst) + bias + relu ----------------
__global__ void __launch_bounds__(128) agg512_kernel(
    const float* __restrict__ h, const float* __restrict__ bias, float* __restrict__ out)
{
    int dst = blockIdx.x, t = threadIdx.x;
    float wd = g_dinv[dst];
    float4 acc = *(const float4*)(h + (size_t)dst * 512 + t * 4);
    float ws = wd * wd;
    acc.x *= ws; acc.y *= ws; acc.z *= ws; acc.w *= ws;
    int e0 = g_offs[dst], e1 = g_offs[dst + 1];
    for (int e = e0; e < e1; e++) {
        int s = g_csrc[e];
        float w = g_dinv[s] * wd;
        float4 v = *(const float4*)(h + (size_t)s * 512 + t * 4);
        acc.x += v.x * w; acc.y += v.y * w; acc.z += v.z * w; acc.w += v.w * w;
    }
    float4 bb = *(const float4*)(bias + t * 4);
    float4 r;
    r.x = fmaxf(acc.x + bb.x, 0.f);
    r.y = fmaxf(acc.y + bb.y, 0.f);
    r.z = fmaxf(acc.z + bb.z, 0.f);
    r.w = fmaxf(acc.w + bb.w, 0.f);
    *(float4*)(out + (size_t)dst * 512 + t * 4) = r;
}

__global__ void __launch_bounds__(128) agg256_kernel(
    const float* __restrict__ h, const float* __restrict__ bias, float* __restrict__ out)
{
    int dst = blockIdx.x, t = threadIdx.x;
    float wd = g_dinv[dst];
    float2 acc = *(const float2*)(h + (size_t)dst * 256 + t * 2);
    float ws = wd * wd;
    acc.x *= ws; acc.y *= ws;
    int e0 = g_offs[dst], e1 = g_offs[dst + 1];
    for (int e = e0; e < e1; e++) {
        int s = g_csrc[e];
        float w = g_dinv[s] * wd;
        float2 v = *(const float2*)(h + (size_t)s * 256 + t * 2);
        acc.x += v.x * w; acc.y += v.y * w;
    }
    float2 bb = *(const float2*)(bias + t * 2);
    float2 r;
    r.x = fmaxf(acc.x + bb.x, 0.f);
    r.y = fmaxf(acc.y + bb.y, 0.f);
    *(float2*)(out + (size_t)dst * 256 + t * 2) = r;
}

__global__ void __launch_bounds__(128) agg128_kernel(
    const float* __restrict__ h, const float* __restrict__ bias, float* __restrict__ out)
{
    int dst = blockIdx.x, t = threadIdx.x;
    float wd = g_dinv[dst];
    float acc = h[(size_t)dst * 128 + t] * wd * wd;
    int e0 = g_offs[dst], e1 = g_offs[dst + 1];
    for (int e = e0; e < e1; e++) {
        int s = g_csrc[e];
        acc += h[(size_t)s * 128 + t] * (g_dinv[s] * wd);
    }
    out[(size_t)dst * 128 + t] = fmaxf(acc + bias[t], 0.f);
}

// ---------------- gate scores: gate[i] = dot(x[i,0:512], gate_w) + gate_b ----------------
__global__ void __launch_bounds__(256) gate_kernel(const float* __restrict__ gw,
                                                   const float* __restrict__ gb)
{
    int warp = (blockIdx.x * blockDim.x + threadIdx.x) >> 5;
    int lane = threadIdx.x & 31;
    if (warp >= N_NODES) return;
    const float* xr = g_buf0 + (size_t)warp * 512;
    float s = 0.f;
#pragma unroll 4
    for (int k = lane; k < 512; k += 32) s += xr[k] * gw[k];
#pragma unroll
    for (int o = 16; o > 0; o >>= 1) s += __shfl_xor_sync(0xffffffffu, s, o);
    if (lane == 0) g_gate[warp] = s + gb[0];
}

// ---------------- segment softmax + weighted sum -> graph embeddings [G, 512] ----------------
__global__ void __launch_bounds__(256) softmax_emb_kernel()
{
    __shared__ float red[8];
    __shared__ float salpha[256];
    __shared__ float bcast;
    int g = blockIdx.x, tid = threadIdx.x;
    int lane = tid & 31, wid = tid >> 5;
    int s = g_goffs[g], e = g_goffs[g + 1];

    // block max
    float m = -INFINITY;
    for (int i = s + tid; i < e; i += 256) m = fmaxf(m, g_gate[i]);
#pragma unroll
    for (int o = 16; o > 0; o >>= 1) m = fmaxf(m, __shfl_xor_sync(0xffffffffu, m, o));
    if (lane == 0) red[wid] = m;
    __syncthreads();
    if (wid == 0) {
        float t = (lane < 8) ? red[lane] : -INFINITY;
#pragma unroll
        for (int o = 4; o > 0; o >>= 1) t = fmaxf(t, __shfl_xor_sync(0xffffffffu, t, o));
        if (lane == 0) bcast = t;
    }
    __syncthreads();
    m = bcast;

    // block sum of exp
    float sum = 0.f;
    for (int i = s + tid; i < e; i += 256) sum += expf(g_gate[i] - m);
#pragma unroll
    for (int o = 16; o > 0; o >>= 1) sum += __shfl_xor_sync(0xffffffffu, sum, o);
    if (lane == 0) red[wid] = sum;
    __syncthreads();
    if (wid == 0) {
        float t = (lane < 8) ? red[lane] : 0.f;
#pragma unroll
        for (int o = 4; o > 0; o >>= 1) t += __shfl_xor_sync(0xffffffffu, t, o);
        if (lane == 0) bcast = t;
    }
    __syncthreads();
    float inv = (e > s) ? 1.f / bcast : 0.f;

    // weighted accumulation: thread owns columns tid and tid+256
    float acc0 = 0.f, acc1 = 0.f;
    for (int start = s; start < e; start += 256) {
        int i = start + tid;
        salpha[tid] = (i < e) ? expf(g_gate[i] - m) * inv : 0.f;
        __syncthreads();
        int cnt = min(256, e - start);
        for (int k = 0; k < cnt; k++) {
            float a = salpha[k];
            const float* xr = g_buf0 + (size_t)(start + k) * 512;
            acc0 += xr[tid] * a;
            acc1 += xr[tid + 256] * a;
        }
        __syncthreads();
    }
    g_emb[g * 512 + tid] = acc0;
    g_emb[g * 512 + 256 + tid] = acc1;
}

// ---------------- GRU cell with h=0: out = (1-z)*n ; gh = bhh (whh unused) ----------------
__global__ void __launch_bounds__(256) gru_cell_kernel(
    const float* __restrict__ xin, const float* __restrict__ wih,
    const float* __restrict__ bih, const float* __restrict__ bhh,
    float* __restrict__ hout, int K)
{
    int warp = (blockIdx.x * blockDim.x + threadIdx.x) >> 5;
    int lane = threadIdx.x & 31;
    if (warp >= N_GRAPHS * GRUH) return;
    int g = warp >> 8;
    int j = warp & 255;
    const float* xg = xin + (size_t)g * K;
    const float* wr = wih + (size_t)j * K;
    const float* wz = wih + (size_t)(j + 256) * K;
    const float* wn = wih + (size_t)(j + 512) * K;
    float sr = 0.f, sz = 0.f, sn = 0.f;
    for (int k = lane; k < K; k += 32) {
        float xv = xg[k];
        sr += xv * wr[k];
        sz += xv * wz[k];
        sn += xv * wn[k];
    }
#pragma unroll
    for (int o = 16; o > 0; o >>= 1) {
        sr += __shfl_xor_sync(0xffffffffu, sr, o);
        sz += __shfl_xor_sync(0xffffffffu, sz, o);
        sn += __shfl_xor_sync(0xffffffffu, sn, o);
    }
    if (lane == 0) {
        float r = 1.f / (1.f + expf(-(sr + bih[j] + bhh[j])));
        float z = 1.f / (1.f + expf(-(sz + bih[j + 256] + bhh[j + 256])));
        float n = tanhf(sn + bih[j + 512] + r * bhh[j + 512]);
        hout[g * GRUH + j] = (1.f - z) * n;
    }
}

// ---------------- output projection: out[g,o] = dot(h2[g], proj_w[o]) + proj_b[o] ----------------
__global__ void __launch_bounds__(256) proj_kernel(
    const float* __restrict__ h2, const float* __restrict__ pw,
    const float* __restrict__ pb, float* __restrict__ out)
{
    int warp = (blockIdx.x * blockDim.x + threadIdx.x) >> 5;
    int lane = threadIdx.x & 31;
    if (warp >= N_GRAPHS * 512) return;
    int g = warp >> 9;
    int o = warp & 511;
    const float* hr = h2 + (size_t)g * 256;
    const float* wr = pw + (size_t)o * 256;
    float s = 0.f;
#pragma unroll 4
    for (int k = lane; k < 256; k += 32) s += hr[k] * wr[k];
#pragma unroll
    for (int d = 16; d > 0; d >>= 1) s += __shfl_xor_sync(0xffffffffu, s, d);
    if (lane == 0) out[g * 512 + o] = s + pb[o];
}

// ---------------- launch ----------------
extern "C" void kernel_launch(void* const* d_in, const int* in_sizes, int n_in,
                              void* d_out, int out_size)
{
    const float* x       = (const float*)d_in[0];
    const void*  ei      = d_in[1];
    const void*  batch   = d_in[2];
    const float* w0 = (const float*)d_in[3];  const float* b0 = (const float*)d_in[4];
    const float* w1 = (const float*)d_in[5];  const float* b1 = (const float*)d_in[6];
    const float* w2 = (const float*)d_in[7];  const float* b2 = (const float*)d_in[8];
    const float* gate_w = (const float*)d_in[9];
    const float* gate_b = (const float*)d_in[10];
    const float* wih0 = (const float*)d_in[11];
    const float* bih0 = (const float*)d_in[13];
    const float* bhh0 = (const float*)d_in[14];
    const float* wih1 = (const float*)d_in[15];
    const float* bih1 = (const float*)d_in[17];
    const float* bhh1 = (const float*)d_in[18];
    const float* proj_w = (const float*)d_in[19];
    const float* proj_b = (const float*)d_in[20];
    float* out = (float*)d_out;

    float *pH, *pB0, *pB1, *pEmb, *pH1, *pH2;
    cudaGetSymbolAddress((void**)&pH,   g_h);
    cudaGetSymbolAddress((void**)&pB0,  g_buf0);
    cudaGetSymbolAddress((void**)&pB1,  g_buf1);
    cudaGetSymbolAddress((void**)&pEmb, g_emb);
    cudaGetSymbolAddress((void**)&pH1,  g_h1);
    cudaGetSymbolAddress((void**)&pH2,  g_h2);

    // preprocessing: index width, degrees, CSR, norms
    detect_kernel<<<1, 32>>>((const int*)ei);
    init_kernel<<<256, 256>>>();
    count_kernel<<<1024, 256>>>(ei, batch);
    scan_kernel<<<1, 1024>>>();
    dinv_kernel<<<(N_NODES + 255) / 256, 256>>>();
    fill_kernel<<<1024, 256>>>(ei);

    dim3 gA((N_NODES + BM - 1) / BM, 1);

    // GCN layer 0: 64 -> 128
    sgemm_kernel<<<dim3(gA.x, 128 / BN), 256>>>(x, w0, pH, N_NODES, 128, 64);
    agg128_kernel<<<N_NODES, 128>>>(pH, b0, pB0);
    // GCN layer 1: 128 -> 256
    sgemm_kernel<<<dim3(gA.x, 256 / BN), 256>>>(pB0, w1, pH, N_NODES, 256, 128);
    agg256_kernel<<<N_NODES, 128>>>(pH, b1, pB1);
    // GCN layer 2: 256 -> 512
    sgemm_kernel<<<dim3(gA.x, 512 / BN), 256>>>(pB1, w2, pH, N_NODES, 512, 256);
    agg512_kernel<<<N_NODES, 128>>>(pH, b2, pB0);

    // attentional aggregation
    gate_kernel<<<(N_NODES * 32 + 255) / 256, 256>>>(gate_w, gate_b);
    softmax_emb_kernel<<<N_GRAPHS, 256>>>();

    // GRU (seq_len=1, h0=0 for both cells) + projection
    gru_cell_kernel<<<(N_GRAPHS * GRUH * 32) / 256, 256>>>(pEmb, wih0, bih0, bhh0, pH1, 512);
    gru_cell_kernel<<<(N_GRAPHS * GRUH * 32) / 256, 256>>>(pH1, wih1, bih1, bhh1, pH2, 256);
    proj_kernel<<<(N_GRAPHS * 512 * 32) / 256, 256>>>(pH2, proj_w, proj_b, out);
}